// round 7
// baseline (speedup 1.0000x reference)
#include <cuda_runtime.h>
#include <math.h>

#define BB   4
#define SEQ  2048
#define HH   16
#define DK   64
#define DM   1024
#define PAD  68          // 64 + 4 floats row stride in smem (16B-aligned float4 rows)
#define LN_EPS 1e-5f

// ---------------- scratch (device globals: no allocations allowed) ----------
__device__ float g_Q[(size_t)BB * HH * SEQ * DK];   // [b][h][s][dk]
__device__ float g_K[(size_t)BB * HH * SEQ * DK];
__device__ float g_V[(size_t)BB * HH * SEQ * DK];
__device__ float g_O[(size_t)BB * SEQ * DM];        // [b][s][d]

#define GETC(v, t) ((t) == 0 ? (v).x : (t) == 1 ? (v).y : (t) == 2 ? (v).z : (v).w)

// =====================================================================
// Kernel 1: per-head QKV projection.
// One block = (b, h, 64-row s-tile). 256 threads, 16x16 grid, 4x4 register
// tiles for each of Q/K/V. W tiles + x tile staged in smem.
// =====================================================================
__global__ __launch_bounds__(256)
void qkv_kernel(const float* __restrict__ x,
                const float* __restrict__ Wq, const float* __restrict__ Wk,
                const float* __restrict__ Wv,
                const float* __restrict__ bq, const float* __restrict__ bk,
                const float* __restrict__ bv)
{
    extern __shared__ float sm[];
    float* Xs  = sm;                 // [64][PAD]  rows = s, cols = d_in
    float* WQs = Xs  + 64 * PAD;     // [64][PAD]  rows = d_in, cols = d_out
    float* WKs = WQs + 64 * PAD;
    float* WVs = WKs + 64 * PAD;

    const int bt  = blockIdx.x;
    const int it  = bt & 31;
    const int h   = (bt >> 5) & 15;
    const int b   = bt >> 9;
    const int tid = threadIdx.x;
    const int s0  = it * 64;

    const float* wq = Wq + h * 4096;
    const float* wk = Wk + h * 4096;
    const float* wv = Wv + h * 4096;

    for (int i = tid; i < 1024; i += 256) {
        int off = i * 4;
        int r = off >> 6, c = off & 63;
        *(float4*)(Xs  + r * PAD + c) =
            *(const float4*)(x + ((size_t)(b * SEQ + s0 + r)) * DM + h * DK + c);
        *(float4*)(WQs + r * PAD + c) = *(const float4*)(wq + off);
        *(float4*)(WKs + r * PAD + c) = *(const float4*)(wk + off);
        *(float4*)(WVs + r * PAD + c) = *(const float4*)(wv + off);
    }
    __syncthreads();

    const int tx = tid & 15, ty = tid >> 4;
    const int r0 = ty * 4, c0 = tx * 4;

    float aq[4][4] = {}, ak[4][4] = {}, av[4][4] = {};

    for (int d0 = 0; d0 < 64; d0 += 4) {
        float4 xf[4];
        #pragma unroll
        for (int ii = 0; ii < 4; ii++)
            xf[ii] = *(float4*)(Xs + (r0 + ii) * PAD + d0);
        #pragma unroll
        for (int t = 0; t < 4; t++) {
            float4 q4 = *(float4*)(WQs + (d0 + t) * PAD + c0);
            float4 k4 = *(float4*)(WKs + (d0 + t) * PAD + c0);
            float4 v4 = *(float4*)(WVs + (d0 + t) * PAD + c0);
            #pragma unroll
            for (int ii = 0; ii < 4; ii++) {
                float xv = GETC(xf[ii], t);
                aq[ii][0] += xv * q4.x; aq[ii][1] += xv * q4.y;
                aq[ii][2] += xv * q4.z; aq[ii][3] += xv * q4.w;
                ak[ii][0] += xv * k4.x; ak[ii][1] += xv * k4.y;
                ak[ii][2] += xv * k4.z; ak[ii][3] += xv * k4.w;
                av[ii][0] += xv * v4.x; av[ii][1] += xv * v4.y;
                av[ii][2] += xv * v4.z; av[ii][3] += xv * v4.w;
            }
        }
    }

    float4 bq4 = *(const float4*)(bq + h * 64 + c0);
    float4 bk4 = *(const float4*)(bk + h * 64 + c0);
    float4 bv4 = *(const float4*)(bv + h * 64 + c0);

    size_t base = ((size_t)(b * HH + h) * SEQ + (s0 + r0)) * DK + c0;
    #pragma unroll
    for (int ii = 0; ii < 4; ii++) {
        size_t o = base + (size_t)ii * DK;
        *(float4*)(g_Q + o) = make_float4(aq[ii][0] + bq4.x, aq[ii][1] + bq4.y,
                                          aq[ii][2] + bq4.z, aq[ii][3] + bq4.w);
        *(float4*)(g_K + o) = make_float4(ak[ii][0] + bk4.x, ak[ii][1] + bk4.y,
                                          ak[ii][2] + bk4.z, ak[ii][3] + bk4.w);
        *(float4*)(g_V + o) = make_float4(av[ii][0] + bv4.x, av[ii][1] + bv4.y,
                                          av[ii][2] + bv4.z, av[ii][3] + bv4.w);
    }
}

// =====================================================================
// Kernel 2: flash attention (fp32, online softmax).
// One block = (b, h, 64-row query tile). 256 threads, 16x16 grid,
// each thread owns a 4x4 tile of S/P and a 4x4 tile of O.
// K is stored transposed in smem so all inner-loop float4 LDS are either
// lane-broadcast (Q, P rows) or contiguous across tx (K^T, V rows).
// =====================================================================
__global__ __launch_bounds__(256)
void attn_kernel()
{
    extern __shared__ float sm[];
    float* Qs   = sm;                  // [row(q)][dk]
    float* Kst  = Qs  + 64 * PAD;      // [dk][key]   (transposed)
    float* Vs   = Kst + 64 * PAD;      // [key][dk]
    float* Ps   = Vs  + 64 * PAD;      // [row(q)][key]
    float* red  = Ps  + 64 * PAD;      // [64][16] partial reductions
    float* mrow = red + 64 * 16;       // [64]
    float* lrow = mrow + 64;           // [64]
    float* arow = lrow + 64;           // [64]

    const int bt  = blockIdx.x;
    const int it  = bt & 31;
    const int h   = (bt >> 5) & 15;
    const int b   = bt >> 9;
    const int tid = threadIdx.x;
    const int tx  = tid & 15, ty = tid >> 4;
    const int r0  = ty * 4,  c0 = tx * 4;

    const size_t bh = (size_t)(b * HH + h) * SEQ;
    const float* Qg = g_Q + bh * DK;
    const float* Kg = g_K + bh * DK;
    const float* Vg = g_V + bh * DK;

    // load Q tile
    for (int i = tid; i < 1024; i += 256) {
        int off = i * 4;
        int r = off >> 6, c = off & 63;
        *(float4*)(Qs + r * PAD + c) =
            *(const float4*)(Qg + (size_t)(it * 64 + r) * DK + c);
    }
    if (tid < 64) { mrow[tid] = -1e30f; lrow[tid] = 0.0f; }

    float o[4][4] = {};
    __syncthreads();

    for (int j = 0; j < 32; j++) {
        // ---- stage K^T and V for this key tile ----
        for (int i = tid; i < 1024; i += 256) {
            int off = i * 4;
            int key = off >> 6, d = off & 63;
            float4 kv = *(const float4*)(Kg + (size_t)(j * 64 + key) * DK + d);
            Kst[(d + 0) * PAD + key] = kv.x;
            Kst[(d + 1) * PAD + key] = kv.y;
            Kst[(d + 2) * PAD + key] = kv.z;
            Kst[(d + 3) * PAD + key] = kv.w;
            *(float4*)(Vs + key * PAD + d) =
                *(const float4*)(Vg + (size_t)(j * 64 + key) * DK + d);
        }
        __syncthreads();

        // ---- S = (Q K^T) * 1/sqrt(dk) ----
        float sacc[4][4] = {};
        for (int kk = 0; kk < 64; kk += 4) {
            float4 qf[4];
            #pragma unroll
            for (int ii = 0; ii < 4; ii++)
                qf[ii] = *(float4*)(Qs + (r0 + ii) * PAD + kk);
            #pragma unroll
            for (int t = 0; t < 4; t++) {
                float4 kf = *(float4*)(Kst + (kk + t) * PAD + c0);
                #pragma unroll
                for (int ii = 0; ii < 4; ii++) {
                    float qv = GETC(qf[ii], t);
                    sacc[ii][0] += qv * kf.x; sacc[ii][1] += qv * kf.y;
                    sacc[ii][2] += qv * kf.z; sacc[ii][3] += qv * kf.w;
                }
            }
        }
        // scale + per-thread row-max partials
        #pragma unroll
        for (int ii = 0; ii < 4; ii++) {
            float pm = -1e30f;
            #pragma unroll
            for (int jj = 0; jj < 4; jj++) {
                sacc[ii][jj] *= 0.125f;          // 1/sqrt(64)
                pm = fmaxf(pm, sacc[ii][jj]);
            }
            red[(r0 + ii) * 16 + tx] = pm;
        }
        __syncthreads();

        // ---- running max / rescale factor ----
        if (tid < 64) {
            float mo = mrow[tid];
            float mn = mo;
            #pragma unroll
            for (int t = 0; t < 16; t++) mn = fmaxf(mn, red[tid * 16 + t]);
            arow[tid] = __expf(mo - mn);
            mrow[tid] = mn;
        }
        __syncthreads();

        // ---- P = exp(S - m), write to smem, rowsum partials, rescale O ----
        #pragma unroll
        for (int ii = 0; ii < 4; ii++) {
            float mn = mrow[r0 + ii];
            float a  = arow[r0 + ii];
            float ps = 0.0f;
            #pragma unroll
            for (int jj = 0; jj < 4; jj++) {
                float p = __expf(sacc[ii][jj] - mn);
                Ps[(r0 + ii) * PAD + c0 + jj] = p;
                ps += p;
                o[ii][jj] *= a;
            }
            red[(r0 + ii) * 16 + tx] = ps;
        }
        __syncthreads();

        if (tid < 64) {
            float s = 0.0f;
            #pragma unroll
            for (int t = 0; t < 16; t++) s += red[tid * 16 + t];
            lrow[tid] = lrow[tid] * arow[tid] + s;
        }

        // ---- O += P V ----
        for (int kk = 0; kk < 64; kk += 4) {
            float4 pf[4];
            #pragma unroll
            for (int ii = 0; ii < 4; ii++)
                pf[ii] = *(float4*)(Ps + (r0 + ii) * PAD + kk);
            #pragma unroll
            for (int t = 0; t < 4; t++) {
                float4 vf = *(float4*)(Vs + (kk + t) * PAD + c0);
                #pragma unroll
                for (int ii = 0; ii < 4; ii++) {
                    float pv = GETC(pf[ii], t);
                    o[ii][0] += pv * vf.x; o[ii][1] += pv * vf.y;
                    o[ii][2] += pv * vf.z; o[ii][3] += pv * vf.w;
                }
            }
        }
        __syncthreads();   // protects Kst/Vs/Ps/red for next tile
    }

    // ---- epilogue: normalize by l and write O as [b][s][h*64+c] ----
    #pragma unroll
    for (int ii = 0; ii < 4; ii++) {
        float li = 1.0f / lrow[r0 + ii];
        size_t off = ((size_t)b * SEQ + (size_t)(it * 64 + r0 + ii)) * DM + h * 64 + c0;
        *(float4*)(g_O + off) = make_float4(o[ii][0] * li, o[ii][1] * li,
                                            o[ii][2] * li, o[ii][3] * li);
    }
}

// =====================================================================
// Kernel 3: residual + LayerNorm. One block per (b,s) row, 256 threads.
// =====================================================================
__global__ __launch_bounds__(256)
void ln_kernel(const float* __restrict__ x,
               const float* __restrict__ gamma,
               const float* __restrict__ beta,
               float* __restrict__ out)
{
    const int row = blockIdx.x;
    const int tid = threadIdx.x;
    const float* xr = x   + (size_t)row * DM;
    const float* orow = g_O + (size_t)row * DM;

    float y[4];
    float s1 = 0.0f, s2 = 0.0f;
    #pragma unroll
    for (int k = 0; k < 4; k++) {
        int d = tid + k * 256;
        float v = orow[d] + xr[d];
        y[k] = v;
        s1 += v;
        s2 += v * v;
    }
    // intra-warp reduce
    #pragma unroll
    for (int off = 16; off > 0; off >>= 1) {
        s1 += __shfl_xor_sync(0xFFFFFFFFu, s1, off);
        s2 += __shfl_xor_sync(0xFFFFFFFFu, s2, off);
    }
    __shared__ float r1[8], r2[8];
    __shared__ float sm_mean, sm_rstd;
    if ((tid & 31) == 0) { r1[tid >> 5] = s1; r2[tid >> 5] = s2; }
    __syncthreads();
    if (tid == 0) {
        float t1 = 0.0f, t2 = 0.0f;
        #pragma unroll
        for (int w = 0; w < 8; w++) { t1 += r1[w]; t2 += r2[w]; }
        float mean = t1 * (1.0f / DM);
        float var  = t2 * (1.0f / DM) - mean * mean;
        sm_mean = mean;
        sm_rstd = rsqrtf(var + LN_EPS);
    }
    __syncthreads();
    float mean = sm_mean, rstd = sm_rstd;
    float* orow_out = out + (size_t)row * DM;
    #pragma unroll
    for (int k = 0; k < 4; k++) {
        int d = tid + k * 256;
        orow_out[d] = (y[k] - mean) * rstd * gamma[d] + beta[d];
    }
}

// =====================================================================
extern "C" void kernel_launch(void* const* d_in, const int* in_sizes, int n_in,
                              void* d_out, int out_size)
{
    const float* x     = (const float*)d_in[0];
    const float* Wq    = (const float*)d_in[1];
    const float* Wk    = (const float*)d_in[2];
    const float* Wv    = (const float*)d_in[3];
    const float* bq    = (const float*)d_in[4];
    const float* bk    = (const float*)d_in[5];
    const float* bv    = (const float*)d_in[6];
    const float* gamma = (const float*)d_in[7];
    const float* beta  = (const float*)d_in[8];
    float* out = (float*)d_out;

    const int qkv_smem = 4 * 64 * PAD * (int)sizeof(float);                  // 69632 B
    const int att_smem = (4 * 64 * PAD + 64 * 16 + 3 * 64) * (int)sizeof(float); // 74496 B

    cudaFuncSetAttribute(qkv_kernel, cudaFuncAttributeMaxDynamicSharedMemorySize, qkv_smem);
    cudaFuncSetAttribute(attn_kernel, cudaFuncAttributeMaxDynamicSharedMemorySize, att_smem);

    qkv_kernel<<<BB * HH * (SEQ / 64), 256, qkv_smem>>>(x, Wq, Wk, Wv, bq, bk, bv);
    attn_kernel<<<BB * HH * (SEQ / 64), 256, att_smem>>>();
    ln_kernel<<<BB * SEQ, 256>>>(x, gamma, beta, out);
}